// round 1
// baseline (speedup 1.0000x reference)
#include <cuda_runtime.h>
#include <cstdint>

#define D      50
#define DP     52        // padded row (13 x float4)
#define NF2    26        // float2 slots per row incl. pad
#define KT     64        // K-tile held in smem
#define TPB    64        // threads per CTA = rows per CTA

// Packed dual-FP32 FMA (Blackwell): 2 FMAs per issue slot vs 1 for 3-reg FFMA.
__device__ __forceinline__ float2 ffma2(float2 a, float2 b, float2 c) {
    float2 d;
    asm("fma.rn.f32x2 %0, %1, %2, %3;"
        : "=l"(reinterpret_cast<unsigned long long&>(d))
        : "l"(reinterpret_cast<const unsigned long long&>(a)),
          "l"(reinterpret_cast<const unsigned long long&>(b)),
          "l"(reinterpret_cast<const unsigned long long&>(c)));
    return d;
}

__global__ __launch_bounds__(TPB)
void memread_fused_kernel(const float* __restrict__ x,
                          const float* __restrict__ mem,
                          float* __restrict__ out,
                          int B, int K)
{
    __shared__ __align__(16) float mt[KT][DP];

    const int tid = threadIdx.x;
    const int row = blockIdx.x * TPB + tid;
    const bool active = (row < B);

    // Per-thread row of X (float2-packed dims; rows are 200B => 8B aligned always)
    float2 xv[NF2];
    float2 av[NF2];
    if (active) {
        const float2* xr = reinterpret_cast<const float2*>(x + (size_t)row * D);
        #pragma unroll
        for (int j = 0; j < 25; ++j) xv[j] = xr[j];
    } else {
        #pragma unroll
        for (int j = 0; j < 25; ++j) xv[j] = make_float2(0.f, 0.f);
    }
    xv[25] = make_float2(0.f, 0.f);            // pad dims 50,51
    #pragma unroll
    for (int j = 0; j < NF2; ++j) av[j] = make_float2(0.f, 0.f);

    // Zero the pad columns once; tile loads below never touch d>=50.
    for (int k = tid; k < KT; k += TPB) { mt[k][50] = 0.f; mt[k][51] = 0.f; }

    const int KD = K * D;
    for (int t = 0; t < K; t += KT) {
        __syncthreads();  // previous tile fully consumed
        // Cooperative load of memory[t : t+KT, :] (zero-fill past K; a zero m-row
        // contributes exp(0)*0 = 0 to the accumulator, so tails are safe).
        const int base = t * D;
        #pragma unroll 1
        for (int i = tid; i < KT * D; i += TPB) {
            int k = i / D;
            int d = i - k * D;
            float v = (base + i < KD) ? mem[base + i] : 0.f;
            mt[k][d] = v;
        }
        __syncthreads();

        #pragma unroll 1
        for (int k = 0; k < KT; ++k) {
            const float4* mrow = reinterpret_cast<const float4*>(&mt[k][0]);

            // ---- dot(x_row, m_k): 4 independent packed accumulators ----
            float2 d0 = make_float2(0.f, 0.f), d1 = d0, d2 = d0, d3 = d0;
            #pragma unroll
            for (int j = 0; j < 13; ++j) {
                float4 m4 = mrow[j];                       // broadcast LDS.128
                float2 mlo = make_float2(m4.x, m4.y);
                float2 mhi = make_float2(m4.z, m4.w);
                if (j & 1) {
                    d2 = ffma2(xv[2*j],   mlo, d2);
                    d3 = ffma2(xv[2*j+1], mhi, d3);
                } else {
                    d0 = ffma2(xv[2*j],   mlo, d0);
                    d1 = ffma2(xv[2*j+1], mhi, d1);
                }
            }
            float dot = (d0.x + d0.y) + (d1.x + d1.y)
                      + (d2.x + d2.y) + (d3.x + d3.y);

            float s = __expf(dot);
            float2 s2 = make_float2(s, s);

            // ---- u += s * m_k ----
            #pragma unroll
            for (int j = 0; j < 13; ++j) {
                float4 m4 = mrow[j];
                float2 mlo = make_float2(m4.x, m4.y);
                float2 mhi = make_float2(m4.z, m4.w);
                av[2*j]   = ffma2(s2, mlo, av[2*j]);
                av[2*j+1] = ffma2(s2, mhi, av[2*j+1]);
            }
        }
    }

    if (active) {
        // out row = [x (50) | u_read (50)]; 8B-aligned float2 stores throughout.
        float2* orow = reinterpret_cast<float2*>(out + (size_t)row * (2 * D));
        #pragma unroll
        for (int j = 0; j < 25; ++j) orow[j] = xv[j];
        #pragma unroll
        for (int j = 0; j < 25; ++j) orow[25 + j] = av[j];
    }
}

extern "C" void kernel_launch(void* const* d_in, const int* in_sizes, int n_in,
                              void* d_out, int out_size) {
    const float* x   = (const float*)d_in[0];   // [B, 50]
    const float* mem = (const float*)d_in[1];   // [K, 50]
    float* out       = (float*)d_out;           // [B, 100]

    const int B = in_sizes[0] / D;              // 65536
    const int K = in_sizes[1] / D;              // 2048
    const int grid = (B + TPB - 1) / TPB;       // 1024

    memread_fused_kernel<<<grid, TPB>>>(x, mem, out, B, K);
}

// round 3
// speedup vs baseline: 4.1706x; 4.1706x over previous
#include <cuda_runtime.h>
#include <cuda_bf16.h>
#include <cstdint>

#define DDIM 50
#define MAXK 2048
#define TM   128      // rows per CTA
#define TKT  128      // K-slots per tile

// smem pitches in bf16 elements (chosen for conflict-free 4B fragment loads)
#define PK 72         // [row][d] tiles: 144B pitch -> bank shift 4/row
#define PD 136        // [d][slot] tile: 272B pitch -> bank shift 4/row

// ---------------- static device scratch (pre-split M, two layouts) -----------
__device__ __align__(16) __nv_bfloat16 gMkA[MAXK * 64];   // [slot][d] hi
__device__ __align__(16) __nv_bfloat16 gMkB[MAXK * 64];   // [slot][d] lo
__device__ __align__(16) __nv_bfloat16 gMdA[64 * MAXK];   // [d][slot] hi
__device__ __align__(16) __nv_bfloat16 gMdB[64 * MAXK];   // [d][slot] lo

// ---------------- smem layout (bytes) ----------------------------------------
#define SM_XH 0
#define SM_XL (SM_XH + TM * PK * 2)         // 18432
#define SM_KH (SM_XL + TM * PK * 2)
#define SM_KL (SM_KH + TKT * PK * 2)
#define SM_DH (SM_KL + TKT * PK * 2)
#define SM_DL (SM_DH + 64 * PD * 2)
#define SM_TOTAL (SM_DL + 64 * PD * 2)      // 108544 bytes

// ---------------- helpers ----------------------------------------------------
__device__ __forceinline__ uint32_t smem_u32(const void* p) {
    uint32_t a;
    asm("{ .reg .u64 t; cvta.to.shared.u64 t, %1; cvt.u32.u64 %0, t; }" : "=r"(a) : "l"(p));
    return a;
}
__device__ __forceinline__ void sts32(uint32_t addr, uint32_t v) {
    asm volatile("st.shared.b32 [%0], %1;" :: "r"(addr), "r"(v) : "memory");
}
__device__ __forceinline__ uint32_t lds32(uint32_t addr) {
    uint32_t v;
    asm("ld.shared.b32 %0, [%1];" : "=r"(v) : "r"(addr));
    return v;
}
__device__ __forceinline__ uint32_t pack2(float lo, float hi) {   // -> bf16x2
    uint32_t r;
    asm("{ .reg .b16 l, h; cvt.rn.bf16.f32 l, %1; cvt.rn.bf16.f32 h, %2; mov.b32 %0, {l, h}; }"
        : "=r"(r) : "f"(lo), "f"(hi));
    return r;
}
__device__ __forceinline__ float bf16_rt(float v) {               // round-trip
    float r;
    asm("{ .reg .b16 t; cvt.rn.bf16.f32 t, %1; cvt.f32.bf16 %0, t; }" : "=f"(r) : "f"(v));
    return r;
}
// D += A * B   (m16n8k16, row.col, bf16 in, f32 accum)
__device__ __forceinline__ void mma(float* d, const uint32_t* a, uint32_t b0, uint32_t b1) {
    asm volatile(
        "mma.sync.aligned.m16n8k16.row.col.f32.bf16.bf16.f32 "
        "{%0,%1,%2,%3}, {%4,%5,%6,%7}, {%8,%9}, {%0,%1,%2,%3};"
        : "+f"(d[0]), "+f"(d[1]), "+f"(d[2]), "+f"(d[3])
        : "r"(a[0]), "r"(a[1]), "r"(a[2]), "r"(a[3]), "r"(b0), "r"(b1));
}
#define CP16(dst, src) asm volatile("cp.async.cg.shared.global [%0], [%1], 16;" :: "r"(dst), "l"(src))
#define CPCOMMIT()     asm volatile("cp.async.commit_group;" ::: "memory")
#define CPWAIT0()      asm volatile("cp.async.wait_group 0;" ::: "memory")

// ---------------- prep: split M into bf16 hi/lo, two layouts -----------------
__global__ void prep_kernel(const float* __restrict__ mem, int K) {
    int i = blockIdx.x * blockDim.x + threadIdx.x;
    if (i >= K * 64) return;
    int k = i >> 6, d = i & 63;
    float v = (d < DDIM) ? mem[k * DDIM + d] : 0.f;
    float h = bf16_rt(v);
    __nv_bfloat16 hb = __float2bfloat16(h);
    __nv_bfloat16 lb = __float2bfloat16(v - h);
    gMkA[k * 64 + d] = hb;
    gMkB[k * 64 + d] = lb;
    gMdA[d * MAXK + k] = hb;
    gMdB[d * MAXK + k] = lb;
}

// ---------------- main fused kernel ------------------------------------------
__global__ __launch_bounds__(256, 2)
void memread_mma_kernel(const float* __restrict__ x, float* __restrict__ out, int B, int K) {
    extern __shared__ char smem[];
    const uint32_t sb = smem_u32(smem);
    const int tid = threadIdx.x, wid = tid >> 5, lane = tid & 31;
    const int g = lane >> 2, tg = lane & 3;
    const int row0 = blockIdx.x * TM;

    // ---- X: load, passthrough to out[:,0:50], split hi/lo into smem ---------
    for (int w = tid; w < TM * 32; w += 256) {
        int r = w >> 5, dp = w & 31;            // dp = float2 index
        int row = row0 + r;
        float2 v = make_float2(0.f, 0.f);
        if (dp < 25 && row < B) {
            v = *reinterpret_cast<const float2*>(x + (size_t)row * DDIM + dp * 2);
            *reinterpret_cast<float2*>(out + (size_t)row * 100 + dp * 2) = v;
        }
        float hx = bf16_rt(v.x), hy = bf16_rt(v.y);
        uint32_t off = (uint32_t)(r * (PK * 2) + dp * 4);
        sts32(sb + SM_XH + off, pack2(hx, hy));
        sts32(sb + SM_XL + off, pack2(v.x - hx, v.y - hy));
    }
    __syncthreads();

    // ---- persistent X A-fragments (rows wid*16 .. +15, K = d = 0..63) -------
    uint32_t Xh[4][4], Xl[4][4];
    {
        uint32_t base = (uint32_t)((wid * 16 + g) * (PK * 2) + tg * 4);
        #pragma unroll
        for (int ks = 0; ks < 4; ++ks) {
            uint32_t o = base + ks * 32;
            Xh[ks][0] = lds32(sb + SM_XH + o);
            Xh[ks][1] = lds32(sb + SM_XH + o + 8 * PK * 2);
            Xh[ks][2] = lds32(sb + SM_XH + o + 16);
            Xh[ks][3] = lds32(sb + SM_XH + o + 8 * PK * 2 + 16);
            Xl[ks][0] = lds32(sb + SM_XL + o);
            Xl[ks][1] = lds32(sb + SM_XL + o + 8 * PK * 2);
            Xl[ks][2] = lds32(sb + SM_XL + o + 16);
            Xl[ks][3] = lds32(sb + SM_XL + o + 8 * PK * 2 + 16);
        }
    }

    float U[8][4];
    #pragma unroll
    for (int nb = 0; nb < 8; ++nb)
        #pragma unroll
        for (int q = 0; q < 4; ++q) U[nb][q] = 0.f;

    const int ntiles = (K + TKT - 1) / TKT;

    for (int t = 0; t < ntiles; ++t) {
        __syncthreads();                        // previous tile fully consumed
        // ---- cp.async this M tile into smem (both layouts, hi+lo) -----------
        for (int c = tid; c < 1024; c += 256) {
            int r = c >> 3, j = c & 7;          // Mk: 128 rows x 8 x 16B
            uint32_t doff = (uint32_t)(r * (PK * 2) + j * 16);
            const char* srcA = (const char*)(gMkA + (size_t)(t * TKT + r) * 64) + j * 16;
            const char* srcB = (const char*)(gMkB + (size_t)(t * TKT + r) * 64) + j * 16;
            CP16(sb + SM_KH + doff, srcA);
            CP16(sb + SM_KL + doff, srcB);
            int d = c >> 4, j2 = c & 15;        // Md: 64 rows x 16 x 16B
            uint32_t doff2 = (uint32_t)(d * (PD * 2) + j2 * 16);
            const char* srcA2 = (const char*)(gMdA + (size_t)d * MAXK + t * TKT) + j2 * 16;
            const char* srcB2 = (const char*)(gMdB + (size_t)d * MAXK + t * TKT) + j2 * 16;
            CP16(sb + SM_DH + doff2, srcA2);
            CP16(sb + SM_DL + doff2, srcB2);
        }
        CPCOMMIT();
        CPWAIT0();
        __syncthreads();

        // ---- 8 sub-steps: 2 score blocks -> exp -> GEMM2 k-step -------------
        #pragma unroll 1
        for (int s = 0; s < 8; ++s) {
            float C0m[4] = {0, 0, 0, 0}, C0c[4] = {0, 0, 0, 0};
            float C1m[4] = {0, 0, 0, 0}, C1c[4] = {0, 0, 0, 0};
            uint32_t kb = (uint32_t)(((2 * s) * 8 + g) * (PK * 2) + tg * 4);
            #pragma unroll
            for (int ks = 0; ks < 4; ++ks) {
                uint32_t o = kb + ks * 32;
                uint32_t bh0 = lds32(sb + SM_KH + o);
                uint32_t bh1 = lds32(sb + SM_KH + o + 16);
                uint32_t bl0 = lds32(sb + SM_KL + o);
                uint32_t bl1 = lds32(sb + SM_KL + o + 16);
                mma(C0m, Xh[ks], bh0, bh1);     // hi*hi
                mma(C0c, Xh[ks], bl0, bl1);     // hi*lo
                mma(C0c, Xl[ks], bh0, bh1);     // lo*hi
                uint32_t o1 = o + 8 * (PK * 2); // block 2s+1
                uint32_t ch0 = lds32(sb + SM_KH + o1);
                uint32_t ch1 = lds32(sb + SM_KH + o1 + 16);
                uint32_t cl0 = lds32(sb + SM_KL + o1);
                uint32_t cl1 = lds32(sb + SM_KL + o1 + 16);
                mma(C1m, Xh[ks], ch0, ch1);
                mma(C1c, Xh[ks], cl0, cl1);
                mma(C1c, Xl[ks], ch0, ch1);
            }
            // exp + split + pack into GEMM2 A-fragments (register-only S)
            float e0 = __expf(C0m[0] + C0c[0]);
            float e1 = __expf(C0m[1] + C0c[1]);
            float e2 = __expf(C0m[2] + C0c[2]);
            float e3 = __expf(C0m[3] + C0c[3]);
            float e4 = __expf(C1m[0] + C1c[0]);
            float e5 = __expf(C1m[1] + C1c[1]);
            float e6 = __expf(C1m[2] + C1c[2]);
            float e7 = __expf(C1m[3] + C1c[3]);
            float h0 = bf16_rt(e0), h1 = bf16_rt(e1), h2 = bf16_rt(e2), h3 = bf16_rt(e3);
            float h4 = bf16_rt(e4), h5 = bf16_rt(e5), h6 = bf16_rt(e6), h7 = bf16_rt(e7);
            uint32_t ah[4], al[4];
            ah[0] = pack2(h0, h1);  ah[1] = pack2(h2, h3);
            ah[2] = pack2(h4, h5);  ah[3] = pack2(h6, h7);
            al[0] = pack2(e0 - h0, e1 - h1);  al[1] = pack2(e2 - h2, e3 - h3);
            al[2] = pack2(e4 - h4, e5 - h5);  al[3] = pack2(e6 - h6, e7 - h7);

            // GEMM2 k-step s: U[16x64] += S * Md
            uint32_t db = (uint32_t)(g * (PD * 2) + s * 32 + tg * 4);
            #pragma unroll
            for (int nb = 0; nb < 8; ++nb) {
                uint32_t o = db + nb * 8 * (PD * 2);
                uint32_t bh0 = lds32(sb + SM_DH + o);
                uint32_t bh1 = lds32(sb + SM_DH + o + 16);
                uint32_t bl0 = lds32(sb + SM_DL + o);
                uint32_t bl1 = lds32(sb + SM_DL + o + 16);
                mma(U[nb], ah, bh0, bh1);       // s_hi * m_hi
                mma(U[nb], al, bh0, bh1);       // s_lo * m_hi
                mma(U[nb], ah, bl0, bl1);       // s_hi * m_lo
            }
        }
    }

    // ---- writeout U -> out[:, 50:100] ---------------------------------------
    const int r1 = row0 + wid * 16 + g;
    const int r2 = r1 + 8;
    #pragma unroll
    for (int nb = 0; nb < 8; ++nb) {
        int col = nb * 8 + tg * 2;
        if (col < DDIM) {
            if (r1 < B)
                *reinterpret_cast<float2*>(out + (size_t)r1 * 100 + 50 + col) =
                    make_float2(U[nb][0], U[nb][1]);
            if (r2 < B)
                *reinterpret_cast<float2*>(out + (size_t)r2 * 100 + 50 + col) =
                    make_float2(U[nb][2], U[nb][3]);
        }
    }
}

// ---------------- launch -----------------------------------------------------
extern "C" void kernel_launch(void* const* d_in, const int* in_sizes, int n_in,
                              void* d_out, int out_size) {
    const float* x   = (const float*)d_in[0];
    const float* mem = (const float*)d_in[1];
    float* out       = (float*)d_out;
    const int B = in_sizes[0] / DDIM;
    const int K = in_sizes[1] / DDIM;

    cudaFuncSetAttribute(memread_mma_kernel,
                         cudaFuncAttributeMaxDynamicSharedMemorySize, SM_TOTAL);

    prep_kernel<<<(K * 64 + 255) / 256, 256>>>(mem, K);

    const int grid = (B + TM - 1) / TM;
    memread_mma_kernel<<<grid, 256, SM_TOTAL>>>(x, out, B, K);
}